// round 1
// baseline (speedup 1.0000x reference)
#include <cuda_runtime.h>
#include <cstdint>

#define EPSF 1.1920928955078125e-07f

// Problem constants
#define B_   32
#define P_   8192
#define SI_  64
#define SO_  32
#define L_   256
#define C_   4096          // 2 * SI * SO  (flattened side,i,o)
#define YSZ  33554432      // B*P*128

// Device scratch (no allocations allowed)
__device__ float g_logits[B_ * C_];
__device__ float g_V[B_ * C_];
__device__ float g_mask[B_ * C_];
__device__ float g_h[B_ * L_];

// ---------------------------------------------------------------------------
// Kernel 1: logits[b, c] = sum_l latent[b,l] * K[side(c)][l, i, o]
// grid 64 blocks x 256 threads; block covers 64 contiguous cols for all 32 b.
// ---------------------------------------------------------------------------
__global__ void __launch_bounds__(256) k_logits(const float* __restrict__ lat,
                                                const float* __restrict__ Kl,
                                                const float* __restrict__ Kr) {
    __shared__ float slat[B_ * L_];  // 32 KB
    for (int k = threadIdx.x; k < B_ * L_; k += 256) slat[k] = lat[k];
    __syncthreads();

    int c  = blockIdx.x * 64 + (threadIdx.x & 63);
    int bg = threadIdx.x >> 6;  // 0..3 -> batches bg*8 .. bg*8+7
    const float* Ksrc = (c & 2048) ? Kr : Kl;
    int cc = c & 2047;

    float acc[8];
#pragma unroll
    for (int q = 0; q < 8; q++) acc[q] = 0.f;

    for (int l = 0; l < L_; l++) {
        float kv = Ksrc[l * 2048 + cc];
#pragma unroll
        for (int q = 0; q < 8; q++)
            acc[q] += slat[(bg * 8 + q) * L_ + l] * kv;
    }
#pragma unroll
    for (int q = 0; q < 8; q++)
        g_logits[(bg * 8 + q) * C_ + c] = acc[q];
}

// ---------------------------------------------------------------------------
// Kernel 2: per (b, side, o): softmax over i (V), then gumbel-softmax (mask).
// grid 32 (batch) x 64 threads (side*32+o).
// ---------------------------------------------------------------------------
__global__ void __launch_bounds__(64) k_softmax_gumbel(const float* __restrict__ gu,
                                                       const float* __restrict__ temp) {
    int b = blockIdx.x;
    int t = threadIdx.x;                       // side = t>>5, o = t&31
    int base = b * C_ + (t >> 5) * 2048 + (t & 31);

    float v[SI_];
    float mx = -1e30f;
#pragma unroll
    for (int i = 0; i < SI_; i++) { v[i] = g_logits[base + i * 32]; mx = fmaxf(mx, v[i]); }
    float s = 0.f;
#pragma unroll
    for (int i = 0; i < SI_; i++) { v[i] = expf(v[i] - mx); s += v[i]; }
    float inv = 1.0f / s;
#pragma unroll
    for (int i = 0; i < SI_; i++) { v[i] *= inv; g_V[base + i * 32] = v[i]; }

    // gumbel-softmax with temp clipped to [EPS, 2.0]
    float tc = fminf(fmaxf(temp[0], EPSF), 2.0f);
    tc = fmaxf(tc, EPSF);
    float invt = 1.0f / tc;

    mx = -1e30f;
#pragma unroll
    for (int i = 0; i < SI_; i++) {
        float uu = fmaxf(gu[base + i * 32], EPSF);
        float g  = -logf(-logf(uu) + EPSF);
        float lg = (logf(v[i] + EPSF) + g) * invt;
        v[i] = lg;
        mx = fmaxf(mx, lg);
    }
    s = 0.f;
#pragma unroll
    for (int i = 0; i < SI_; i++) { v[i] = expf(v[i] - mx); s += v[i]; }
    inv = 1.0f / s;
#pragma unroll
    for (int i = 0; i < SI_; i++) g_mask[base + i * 32] = v[i] * inv;
}

// ---------------------------------------------------------------------------
// Kernel 3: h[b,j] = leaky( Vflat[b,:] @ W1[:,j] + b1[j] )
// grid 64 = (8 j-tiles x 8 b-tiles of 4), block 128 = (4 b x 32 j).
// W1 read 8x total (32 MB, L2-resident).
// ---------------------------------------------------------------------------
__global__ void __launch_bounds__(128) k_h(const float* __restrict__ W1,
                                           const float* __restrict__ b1) {
    int jt = blockIdx.x & 7;   // 8 x 32 = 256 cols
    int bt = blockIdx.x >> 3;  // 8 x 4  = 32 batches
    int jq = threadIdx.x & 31;
    int bl = threadIdx.x >> 5; // 0..3
    int j  = jt * 32 + jq;
    int b  = bt * 4 + bl;

    __shared__ float Vs[4 * 1024];  // 16 KB tile
    float a0 = 0.f, a1 = 0.f;

    for (int it = 0; it < 4; it++) {
        __syncthreads();
        for (int idx = threadIdx.x; idx < 4096; idx += 128) {
            int bb = idx >> 10, ii = idx & 1023;
            Vs[idx] = g_V[(bt * 4 + bb) * C_ + it * 1024 + ii];
        }
        __syncthreads();
        const float* w = W1 + (size_t)(it * 1024) * 256 + j;
#pragma unroll 4
        for (int k = 0; k < 1024; k += 2) {
            a0 += Vs[bl * 1024 + k]     * w[(size_t)k * 256];
            a1 += Vs[bl * 1024 + k + 1] * w[(size_t)(k + 1) * 256];
        }
    }
    float h = a0 + a1 + b1[j];
    g_h[b * L_ + j] = (h >= 0.f) ? h : 0.01f * h;
}

// ---------------------------------------------------------------------------
// Kernel 4: v_encode[b,j] = h[b,:] @ W2[:,j] + b2[j]  -> tail of d_out
// grid 32 x 256.
// ---------------------------------------------------------------------------
__global__ void __launch_bounds__(256) k_venc(const float* __restrict__ W2,
                                              const float* __restrict__ b2,
                                              float* __restrict__ out) {
    int b = blockIdx.x;
    int j = threadIdx.x;
    __shared__ float sh[L_];
    sh[j] = g_h[b * L_ + j];
    __syncthreads();
    float a0 = 0.f, a1 = 0.f;
#pragma unroll 8
    for (int k = 0; k < L_; k += 2) {
        a0 += sh[k]     * W2[k * L_ + j];
        a1 += sh[k + 1] * W2[(k + 1) * L_ + j];
    }
    out[YSZ + b * L_ + j] = a0 + a1 + b2[j];
}

// ---------------------------------------------------------------------------
// Kernel 5 (main): per row p: yl/yr = x_row @ {mask_l, mask_r}, then
// y = clip([yl+yr, yl+yr-1, yl-yr, yr-yl]).
// Packed fp32x2 FMAs (fma.rn.f32x2) -> 2x FP32 throughput on Blackwell.
// grid (32 p-tiles, 32 batches) x 256 threads, 1 row per thread.
// ---------------------------------------------------------------------------
#define FMA2(acc, a, m) asm("fma.rn.f32x2 %0, %1, %2, %0;" : "+l"(acc) : "l"(a), "l"(m))

__global__ void __launch_bounds__(256) k_main(const float* __restrict__ x,
                                              float* __restrict__ y) {
    __shared__ float sm[SI_ * 64];  // sm[i][0:32]=mask_l[i][:], sm[i][32:64]=mask_r[i][:]
    int tid = threadIdx.x;
    int b = blockIdx.y;
    const float* mb = g_mask + b * C_;

#pragma unroll
    for (int idx = tid; idx < SI_ * 64; idx += 256) {
        int i = idx >> 6, j = idx & 63;
        int side = j >> 5, o = j & 31;
        sm[idx] = mb[side * 2048 + i * 32 + o];
    }
    __syncthreads();

    int p = blockIdx.x * 256 + tid;
    const float4* xr = (const float4*)(x + ((size_t)b * P_ + (size_t)p) * SI_);

    unsigned long long acc[32];
#pragma unroll
    for (int c = 0; c < 32; c++) acc[c] = 0ULL;  // (0.f, 0.f)

#pragma unroll 4
    for (int i4 = 0; i4 < 16; i4++) {
        float4 xv = xr[i4];
        float xs[4] = {xv.x, xv.y, xv.z, xv.w};
#pragma unroll
        for (int s = 0; s < 4; s++) {
            int i = i4 * 4 + s;
            unsigned long long xx;
            asm("mov.b64 %0, {%1, %1};" : "=l"(xx) : "f"(xs[s]));
            const ulonglong2* mrow = (const ulonglong2*)(sm + i * 64);
#pragma unroll
            for (int q = 0; q < 16; q++) {
                ulonglong2 m = mrow[q];   // LDS.128, warp-uniform broadcast
                FMA2(acc[2 * q],     xx, m.x);
                FMA2(acc[2 * q + 1], xx, m.y);
            }
        }
    }

    float yl[32], yr[32];
#pragma unroll
    for (int c = 0; c < 16; c++)
        asm("mov.b64 {%0, %1}, %2;" : "=f"(yl[2 * c]), "=f"(yl[2 * c + 1]) : "l"(acc[c]));
#pragma unroll
    for (int c = 0; c < 16; c++)
        asm("mov.b64 {%0, %1}, %2;" : "=f"(yr[2 * c]), "=f"(yr[2 * c + 1]) : "l"(acc[16 + c]));

    float4* o4 = (float4*)(y + ((size_t)b * P_ + (size_t)p) * 128);
#pragma unroll
    for (int q = 0; q < 8; q++) {
        float s0 = yl[4 * q]     + yr[4 * q];
        float s1 = yl[4 * q + 1] + yr[4 * q + 1];
        float s2 = yl[4 * q + 2] + yr[4 * q + 2];
        float s3 = yl[4 * q + 3] + yr[4 * q + 3];
        float d0 = yl[4 * q]     - yr[4 * q];
        float d1 = yl[4 * q + 1] - yr[4 * q + 1];
        float d2 = yl[4 * q + 2] - yr[4 * q + 2];
        float d3 = yl[4 * q + 3] - yr[4 * q + 3];
#define CLIP01(v) fminf(fmaxf((v), 0.f), 1.f)
        float4 r;
        r.x = CLIP01(s0); r.y = CLIP01(s1); r.z = CLIP01(s2); r.w = CLIP01(s3);
        o4[q] = r;
        r.x = CLIP01(s0 - 1.f); r.y = CLIP01(s1 - 1.f); r.z = CLIP01(s2 - 1.f); r.w = CLIP01(s3 - 1.f);
        o4[8 + q] = r;
        r.x = CLIP01(d0); r.y = CLIP01(d1); r.z = CLIP01(d2); r.w = CLIP01(d3);
        o4[16 + q] = r;
        r.x = CLIP01(-d0); r.y = CLIP01(-d1); r.z = CLIP01(-d2); r.w = CLIP01(-d3);
        o4[24 + q] = r;
#undef CLIP01
    }
}

// ---------------------------------------------------------------------------
extern "C" void kernel_launch(void* const* d_in, const int* in_sizes, int n_in,
                              void* d_out, int out_size) {
    const float* x    = (const float*)d_in[0];
    const float* lat  = (const float*)d_in[1];
    const float* gu   = (const float*)d_in[2];
    const float* Kl   = (const float*)d_in[3];
    const float* Kr   = (const float*)d_in[4];
    const float* temp = (const float*)d_in[5];
    const float* W1   = (const float*)d_in[6];
    const float* b1   = (const float*)d_in[7];
    const float* W2   = (const float*)d_in[8];
    const float* b2   = (const float*)d_in[9];
    float* out = (float*)d_out;

    k_logits<<<64, 256>>>(lat, Kl, Kr);
    k_softmax_gumbel<<<32, 64>>>(gu, temp);
    k_h<<<64, 128>>>(W1, b1);
    k_venc<<<32, 256>>>(W2, b2, out);
    k_main<<<dim3(32, 32), 256>>>(x, out);
}

// round 2
// speedup vs baseline: 2.9764x; 2.9764x over previous
#include <cuda_runtime.h>
#include <cstdint>

#define EPSF 1.1920928955078125e-07f

// Problem constants
#define B_   32
#define P_   8192
#define SI_  64
#define SO_  32
#define L_   256
#define C_   4096          // 2 * SI * SO
#define YSZ  33554432      // B*P*128
#define PST  132           // padded p-stride for transposed x tile

// Device scratch (no allocations allowed)
__device__ float g_logits[B_ * C_];
__device__ float g_V[B_ * C_];
__device__ float g_mask[B_ * C_];
__device__ float g_hp[16 * B_ * L_];   // split-K partials for h

// ---------------------------------------------------------------------------
// Kernel 1: logits[b,c] = sum_l latent[b,l] * K[side(c)][l, i, o]
// grid 128 blocks (32-col tiles) x 256 threads (32 c x 8 batch-groups of 4).
// ---------------------------------------------------------------------------
__global__ void __launch_bounds__(256) k_logits(const float* __restrict__ lat,
                                                const float* __restrict__ Kl,
                                                const float* __restrict__ Kr) {
    __shared__ float slat[B_ * L_];  // 32 KB
    for (int k = threadIdx.x; k < B_ * L_; k += 256) slat[k] = lat[k];
    __syncthreads();

    int c  = blockIdx.x * 32 + (threadIdx.x & 31);
    int bg = threadIdx.x >> 5;                // 0..7 -> batches bg*4..bg*4+3
    const float* Ksrc = (c & 2048) ? Kr : Kl;
    int cc = c & 2047;

    float acc[4] = {0.f, 0.f, 0.f, 0.f};
#pragma unroll 4
    for (int l = 0; l < L_; l++) {
        float kv = Ksrc[(size_t)l * 2048 + cc];
#pragma unroll
        for (int q = 0; q < 4; q++)
            acc[q] += slat[(bg * 4 + q) * L_ + l] * kv;
    }
#pragma unroll
    for (int q = 0; q < 4; q++)
        g_logits[(bg * 4 + q) * C_ + c] = acc[q];
}

// ---------------------------------------------------------------------------
// Kernel 2: warp-per-(b,side,o) column: softmax over i (V), then
// gumbel-softmax (mask). Lane handles i=lane and i=lane+32. Fast-math MUFU.
// grid 256 x 256 (8 warps/block, 2048 columns).
// ---------------------------------------------------------------------------
__device__ __forceinline__ float warp_max(float v) {
#pragma unroll
    for (int m = 16; m > 0; m >>= 1) v = fmaxf(v, __shfl_xor_sync(0xffffffffu, v, m));
    return v;
}
__device__ __forceinline__ float warp_sum(float v) {
#pragma unroll
    for (int m = 16; m > 0; m >>= 1) v += __shfl_xor_sync(0xffffffffu, v, m);
    return v;
}

__global__ void __launch_bounds__(256) k_sg(const float* __restrict__ gu,
                                            const float* __restrict__ temp) {
    int w    = (blockIdx.x * blockDim.x + threadIdx.x) >> 5;  // 0..2047
    int lane = threadIdx.x & 31;
    int rem  = w & 63;
    int base = (w >> 6) * C_ + (rem >> 5) * 2048 + (rem & 31);

    float a0 = g_logits[base + lane * 32];
    float a1 = g_logits[base + (lane + 32) * 32];
    float mx = warp_max(fmaxf(a0, a1));
    float e0 = __expf(a0 - mx), e1 = __expf(a1 - mx);
    float inv = 1.0f / warp_sum(e0 + e1);
    float p0 = e0 * inv, p1 = e1 * inv;
    g_V[base + lane * 32]        = p0;
    g_V[base + (lane + 32) * 32] = p1;

    float tc = fmaxf(fminf(fmaxf(temp[0], EPSF), 2.0f), EPSF);
    float invt = 1.0f / tc;

    float u0 = fmaxf(gu[base + lane * 32], EPSF);
    float u1 = fmaxf(gu[base + (lane + 32) * 32], EPSF);
    float g0 = -__logf(-__logf(u0) + EPSF);
    float g1 = -__logf(-__logf(u1) + EPSF);
    float l0 = (__logf(p0 + EPSF) + g0) * invt;
    float l1 = (__logf(p1 + EPSF) + g1) * invt;
    mx = warp_max(fmaxf(l0, l1));
    e0 = __expf(l0 - mx); e1 = __expf(l1 - mx);
    inv = 1.0f / warp_sum(e0 + e1);
    g_mask[base + lane * 32]        = e0 * inv;
    g_mask[base + (lane + 32) * 32] = e1 * inv;
}

// ---------------------------------------------------------------------------
// Kernel 3: split-K h partials. grid 128 = (8 j-tiles x 16 k-slices),
// block 128 = (32 j x 4 batch-groups of 8). W1 read exactly once (4 MB).
// ---------------------------------------------------------------------------
__global__ void __launch_bounds__(128) k_h_part(const float* __restrict__ W1) {
    int jt = blockIdx.x & 7;
    int ks = blockIdx.x >> 3;

    __shared__ float Vs[B_ * 260];  // padded rows: bank-conflict-free group reads
    for (int idx = threadIdx.x; idx < B_ * 256; idx += 128) {
        int b = idx >> 8, k = idx & 255;
        Vs[b * 260 + k] = g_V[b * C_ + ks * 256 + k];
    }
    __syncthreads();

    int j  = jt * 32 + (threadIdx.x & 31);
    int bq = threadIdx.x >> 5;  // 0..3 -> batches bq*8..bq*8+7

    float acc[8];
#pragma unroll
    for (int q = 0; q < 8; q++) acc[q] = 0.f;

#pragma unroll 4
    for (int k = 0; k < 256; k++) {
        float wv = W1[(size_t)(ks * 256 + k) * 256 + j];
#pragma unroll
        for (int q = 0; q < 8; q++)
            acc[q] += Vs[(bq * 8 + q) * 260 + k] * wv;
    }
#pragma unroll
    for (int q = 0; q < 8; q++)
        g_hp[(ks * B_ + bq * 8 + q) * L_ + j] = acc[q];
}

// ---------------------------------------------------------------------------
// Kernel 4: reduce h partials + bias + leaky, then v_encode = h @ W2 + b2.
// grid 32 (batch) x 512 threads (256 j x 2 k-halves, smem reduce).
// ---------------------------------------------------------------------------
__global__ void __launch_bounds__(512) k_venc(const float* __restrict__ b1,
                                              const float* __restrict__ W2,
                                              const float* __restrict__ b2,
                                              float* __restrict__ out) {
    int b = blockIdx.x;
    int tid = threadIdx.x;
    __shared__ float sh[L_];
    __shared__ float red[L_];

    if (tid < L_) {
        float s = b1[tid];
#pragma unroll
        for (int ks = 0; ks < 16; ks++) s += g_hp[(ks * B_ + b) * L_ + tid];
        sh[tid] = (s >= 0.f) ? s : 0.01f * s;
    }
    __syncthreads();

    int j = tid & 255, half = tid >> 8;
    float a = 0.f;
    const float* wp = W2 + (size_t)(half * 128) * L_ + j;
#pragma unroll 8
    for (int k = 0; k < 128; k++)
        a += sh[half * 128 + k] * wp[(size_t)k * L_];
    if (half) red[j] = a;
    __syncthreads();
    if (!half) out[YSZ + b * L_ + j] = a + red[j] + b2[j];
}

// ---------------------------------------------------------------------------
// Kernel 5 (main): register-tiled GEMM. Block = 128 threads, tile 128p x 64o.
// Thread tile: 8p x (4 yl + 4 yr) -> paired columns so the epilogue
// (s=yl+yr, d=yl-yr, 4 clipped segments) is thread-local.
// x staged transposed in smem (2 chunks of 32 i); packed fma.rn.f32x2.
// grid (64 p-tiles, 32 batches).
// ---------------------------------------------------------------------------
#define FMA2(acc, a, m) asm("fma.rn.f32x2 %0, %1, %2, %0;" : "+l"(acc) : "l"(a), "l"(m))
#define PACK2(d, s)     asm("mov.b64 %0, {%1, %1};" : "=l"(d) : "f"(s))
#define UNPK(lo, hi, s) asm("mov.b64 {%0, %1}, %2;" : "=f"(lo), "=f"(hi) : "l"(s))

__global__ void __launch_bounds__(128) k_main(const float* __restrict__ x,
                                              float* __restrict__ y) {
    __shared__ float sm[SI_ * 64];   // masks: [i][yl 0..31 | yr 0..31]  16 KB
    __shared__ float xs[32 * PST];   // transposed x chunk: [i][p]       16.9 KB

    int tid = threadIdx.x;
    int b = blockIdx.y;
    int pbase = blockIdx.x * 128;

    // masks: g_mask linear (side,i,o) -> sm[i*64 + side*32 + o]
    for (int idx = tid; idx < C_; idx += 128) {
        int side = idx >> 11, rem = idx & 2047;
        sm[(rem >> 5) * 64 + side * 32 + (rem & 31)] = g_mask[b * C_ + idx];
    }

    int og = tid & 7, pg = tid >> 3;
    int o0 = og * 4, p0 = pg * 8;

    unsigned long long al[8][2], ar[8][2];
#pragma unroll
    for (int j = 0; j < 8; j++) { al[j][0] = al[j][1] = 0ULL; ar[j][0] = ar[j][1] = 0ULL; }

    const float* xg = x + ((size_t)b * P_ + pbase) * SI_;

#pragma unroll
    for (int ic = 0; ic < 2; ic++) {
        __syncthreads();
        // stage 128p x 32i transposed
#pragma unroll
        for (int k = 0; k < 8; k++) {
            int idx = tid + k * 128;          // 0..1023
            int p = idx >> 3, f = idx & 7;
            float4 v = *(const float4*)(xg + (size_t)p * SI_ + ic * 32 + f * 4);
            xs[(f * 4 + 0) * PST + p] = v.x;
            xs[(f * 4 + 1) * PST + p] = v.y;
            xs[(f * 4 + 2) * PST + p] = v.z;
            xs[(f * 4 + 3) * PST + p] = v.w;
        }
        __syncthreads();

#pragma unroll 4
        for (int ii = 0; ii < 32; ii++) {
            int i = ic * 32 + ii;
            float4 xa = *(const float4*)&xs[ii * PST + p0];
            float4 xb = *(const float4*)&xs[ii * PST + p0 + 4];
            ulonglong2 ma = *(const ulonglong2*)&sm[i * 64 + o0];        // yl pairs
            ulonglong2 mb = *(const ulonglong2*)&sm[i * 64 + 32 + o0];   // yr pairs

            unsigned long long xx[8];
            PACK2(xx[0], xa.x); PACK2(xx[1], xa.y); PACK2(xx[2], xa.z); PACK2(xx[3], xa.w);
            PACK2(xx[4], xb.x); PACK2(xx[5], xb.y); PACK2(xx[6], xb.z); PACK2(xx[7], xb.w);
#pragma unroll
            for (int j = 0; j < 8; j++) {
                FMA2(al[j][0], xx[j], ma.x);
                FMA2(al[j][1], xx[j], ma.y);
                FMA2(ar[j][0], xx[j], mb.x);
                FMA2(ar[j][1], xx[j], mb.y);
            }
        }
    }

    // epilogue: per row j, 4 paired columns -> 4 segments, float4 stores
    float* yb = y + ((size_t)b * P_ + pbase) * 128;
#define CLIP01(v) fminf(fmaxf((v), 0.f), 1.f)
#pragma unroll
    for (int j = 0; j < 8; j++) {
        float l0, l1, l2, l3, r0, r1, r2, r3;
        UNPK(l0, l1, al[j][0]); UNPK(l2, l3, al[j][1]);
        UNPK(r0, r1, ar[j][0]); UNPK(r2, r3, ar[j][1]);
        float s0 = l0 + r0, s1 = l1 + r1, s2 = l2 + r2, s3 = l3 + r3;
        float d0 = l0 - r0, d1 = l1 - r1, d2 = l2 - r2, d3 = l3 - r3;
        float* row = yb + (size_t)(p0 + j) * 128 + o0;
        float4 v;
        v.x = CLIP01(s0); v.y = CLIP01(s1); v.z = CLIP01(s2); v.w = CLIP01(s3);
        *(float4*)(row) = v;
        v.x = CLIP01(s0 - 1.f); v.y = CLIP01(s1 - 1.f); v.z = CLIP01(s2 - 1.f); v.w = CLIP01(s3 - 1.f);
        *(float4*)(row + 32) = v;
        v.x = CLIP01(d0); v.y = CLIP01(d1); v.z = CLIP01(d2); v.w = CLIP01(d3);
        *(float4*)(row + 64) = v;
        v.x = CLIP01(-d0); v.y = CLIP01(-d1); v.z = CLIP01(-d2); v.w = CLIP01(-d3);
        *(float4*)(row + 96) = v;
    }
#undef CLIP01
}

// ---------------------------------------------------------------------------
extern "C" void kernel_launch(void* const* d_in, const int* in_sizes, int n_in,
                              void* d_out, int out_size) {
    const float* x    = (const float*)d_in[0];
    const float* lat  = (const float*)d_in[1];
    const float* gu   = (const float*)d_in[2];
    const float* Kl   = (const float*)d_in[3];
    const float* Kr   = (const float*)d_in[4];
    const float* temp = (const float*)d_in[5];
    const float* W1   = (const float*)d_in[6];
    const float* b1   = (const float*)d_in[7];
    const float* W2   = (const float*)d_in[8];
    const float* b2   = (const float*)d_in[9];
    float* out = (float*)d_out;

    k_logits<<<128, 256>>>(lat, Kl, Kr);
    k_sg<<<256, 256>>>(gu, temp);
    k_h_part<<<128, 128>>>(W1);
    k_venc<<<32, 512>>>(b1, W2, b2, out);
    k_main<<<dim3(64, 32), 128>>>(x, out);
}